// round 10
// baseline (speedup 1.0000x reference)
#include <cuda_runtime.h>
#include <cfloat>

#define P_PTS    32
#define C_OUT_N  64
#define NACC     54
#define BN_EPS   1e-3
#define NMAX     262144
#define SW2      17            // float4 stride per staged pillar chunk (pad)

typedef unsigned long long ull;

__device__ float  g_acc[NACC];         // statically zero-initialized
__device__ float  g_st[2 * C_OUT_N];   // s[64], t[64]
__device__ float4 g_meta[NMAX];        // (mx, my, mz, npts-as-float-bits)

// ---------------- f32x2 helpers (sm_100+) ----------------
__device__ __forceinline__ ull pack2(float lo, float hi) {
    ull r;
    asm("mov.b64 %0, {%1, %2};" : "=l"(r) : "f"(lo), "f"(hi));
    return r;
}
__device__ __forceinline__ void unpack2(ull v, float& lo, float& hi) {
    asm("mov.b64 {%0, %1}, %2;" : "=f"(lo), "=f"(hi) : "l"(v));
}
__device__ __forceinline__ ull ffma2(ull a, ull b, ull c) {
    ull d;
    asm("fma.rn.f32x2 %0, %1, %2, %3;" : "=l"(d) : "l"(a), "l"(b), "l"(c));
    return d;
}
__device__ __forceinline__ ull fmul2(ull a, ull b) {
    ull d;
    asm("mul.rn.f32x2 %0, %1, %2;" : "=l"(d) : "l"(a), "l"(b));
    return d;
}
// max of the two packed halves (unpack is reg-pair aliasing, costs nothing)
__device__ __forceinline__ float hmax2(ull v) {
    float lo, hi;
    unpack2(v, lo, hi);
    return fmaxf(lo, hi);
}

// ---------------- kernel 1: moment sums (coalesced, chunked smem staging) ----
// 64-thread blocks, 2 warps, each warp owns 32 pillars; two 16-point chunks.
// Reference quirk preserved: u_xyz = (sum over ALL 32 slots)/npts;
// feature-side sums over valid points only. Also writes g_meta (mean + npts).
// REQUIRES g_acc zeroed on entry (static init on first call; k_bn re-zeroes
// after consuming on every call -> graph-replay deterministic).
__global__ void __launch_bounds__(64) k_stats(const float4* __restrict__ vox,
                                              const int* __restrict__ npp,
                                              const float2* __restrict__ cen,
                                              int N)
{
    __shared__ float4 stg[2][32 * SW2];
    __shared__ float  sred[2][NACC];

    int w    = threadIdx.x >> 5;
    int lane = threadIdx.x & 31;
    int pillarBase = blockIdx.x * 64 + w * 32;

    int n = pillarBase + lane;
    bool active = (n < N);
    int npts = 0;
    float cx = 0.f, cy = 0.f;
    if (active) {
        npts = npp[n];
        float2 c = cen[n];
        cx = c.x; cy = c.y;
    }

    float sv[4] = {0.f, 0.f, 0.f, 0.f};
    float sa[3] = {0.f, 0.f, 0.f};
    float g1[10];
#pragma unroll
    for (int i = 0; i < 10; i++) g1[i] = 0.f;

    float4* buf = stg[w];
    int half = lane >> 4;
    int pt   = lane & 15;

    for (int ck = 0; ck < 2; ck++) {
#pragma unroll 4
        for (int q = 0; q < 16; q++) {
            int pidx = pillarBase + 2 * q + half;
            if (pidx < N)
                buf[(2 * q + half) * SW2 + pt] =
                    vox[(size_t)pidx * P_PTS + ck * 16 + pt];
        }
        __syncwarp();

        const float4* my = &buf[lane * SW2];
#pragma unroll 8
        for (int p = 0; p < 16; p++) {
            float4 v = my[p];
            int gp = ck * 16 + p;
            if (active) {
                sa[0] += v.x; sa[1] += v.y; sa[2] += v.z;
                if (gp < npts) {
                    sv[0] += v.x; sv[1] += v.y; sv[2] += v.z; sv[3] += v.w;
                    g1[0] += v.x * v.x; g1[1] += v.x * v.y; g1[2] += v.x * v.z; g1[3] += v.x * v.w;
                    g1[4] += v.y * v.y; g1[5] += v.y * v.z; g1[6] += v.y * v.w;
                    g1[7] += v.z * v.z; g1[8] += v.z * v.w;
                    g1[9] += v.w * v.w;
                }
            }
        }
        __syncwarp();
    }

    float fn  = (float)npts;
    float inv = (npts > 0) ? (1.0f / fn) : 0.0f;
    float u[5] = {sa[0] * inv, sa[1] * inv, sa[2] * inv, cx, cy};

    if (active)
        g_meta[n] = make_float4(u[0], u[1], u[2], __int_as_float(npts));

    float acc[NACC];
    acc[0] = sv[0]; acc[1] = sv[1]; acc[2] = sv[2]; acc[3] = sv[3];
    acc[4] = fn * cx; acc[5] = fn * cy;
#pragma unroll
    for (int i = 0; i < 10; i++) acc[6 + i] = g1[i];
    {
        int idx = 16;
#pragma unroll
        for (int a = 0; a < 4; a++)
#pragma unroll
            for (int k = 0; k < 5; k++) acc[idx++] = sv[a] * u[k];
#pragma unroll
        for (int j = 0; j < 5; j++)
#pragma unroll
            for (int k = j; k < 5; k++) acc[idx++] = fn * u[j] * u[k];
    }
    acc[51] = sa[0]; acc[52] = sa[1]; acc[53] = sa[2];

#pragma unroll
    for (int i = 0; i < NACC; i++) {
#pragma unroll
        for (int off = 16; off; off >>= 1)
            acc[i] += __shfl_xor_sync(0xffffffffu, acc[i], off);
    }
    if (lane == 0) {
#pragma unroll
        for (int i = 0; i < NACC; i++) sred[w][i] = acc[i];
    }
    __syncthreads();
    if (threadIdx.x < NACC)
        atomicAdd(&g_acc[threadIdx.x], sred[0][threadIdx.x] + sred[1][threadIdx.x]);
}

// ---------------- kernel 2: solve BN affine per channel; re-zero g_acc ------
__global__ void k_bn(const float* __restrict__ W,
                     const float* __restrict__ gamma,
                     const float* __restrict__ beta,
                     int N)
{
    int o = threadIdx.x;

    double A[NACC];
    for (int i = 0; i < NACC; i++) A[i] = (double)g_acc[i];

    // all threads have consumed g_acc; re-zero for the next graph replay
    __syncthreads();
    if (o < NACC) g_acc[o] = 0.0f;

    if (o >= C_OUT_N) return;

    const float* w = W + o * 9;
    double w0 = w[0], w1 = w[1], w2 = w[2], w3 = w[3], w4 = w[4];
    double w5 = w[5], w6 = w[6], w7 = w[7], w8 = w[8];

    double Wp[4] = {w0 + w4 + w7, w1 + w5 + w8, w2 + w6, w3};
    double Wt[5] = {w4, w5, w6, w7, w8};

    double NP = (double)N * (double)P_PTS;

    double sumx = Wp[0] * A[0] + Wp[1] * A[1] + Wp[2] * A[2] + Wp[3] * A[3]
                - (Wt[0] * A[51] + Wt[1] * A[52] + Wt[2] * A[53]
                   + Wt[3] * A[4] + Wt[4] * A[5]);
    double mean = sumx / NP;

    const double* G1 = &A[6];
    double q1 = Wp[0] * Wp[0] * G1[0] + 2.0 * Wp[0] * Wp[1] * G1[1]
              + 2.0 * Wp[0] * Wp[2] * G1[2] + 2.0 * Wp[0] * Wp[3] * G1[3]
              + Wp[1] * Wp[1] * G1[4] + 2.0 * Wp[1] * Wp[2] * G1[5]
              + 2.0 * Wp[1] * Wp[3] * G1[6]
              + Wp[2] * Wp[2] * G1[7] + 2.0 * Wp[2] * Wp[3] * G1[8]
              + Wp[3] * Wp[3] * G1[9];

    double q2 = 0.0;
    for (int a = 0; a < 4; a++)
        for (int k = 0; k < 5; k++)
            q2 += Wp[a] * A[16 + a * 5 + k] * Wt[k];
    q2 *= -2.0;

    double q3 = 0.0;
    {
        int idx = 36;
        for (int j = 0; j < 5; j++)
            for (int k = j; k < 5; k++) {
                double f = (j == k) ? 1.0 : 2.0;
                q3 += f * Wt[j] * Wt[k] * A[idx++];
            }
    }

    double E2  = (q1 + q2 + q3) / NP;
    double var = E2 - mean * mean;
    double s   = (double)gamma[o] * rsqrt(var + BN_EPS);
    double t   = (double)beta[o] - mean * s;

    g_st[o]           = (float)s;
    g_st[C_OUT_N + o] = (float)t;
}

// ---------------- kernel 3: s-folded GEMM + max + relu ----------------
// One warp per pillar (grid-stride). Lane l owns channels {l, l+32}; points
// packed in pairs as f32x2 via SoA smem tile; padded slots staged NaN
// (fmaxf ignores them). BN scale s folded INTO the weights; epilogue
// X = M + s*bias, padded pillars clamp X at 0, y = relu(X + t).
// launch_bounds(256,3): cap regs at ~84 (natural 82 fits, no spills) to
// guarantee 3 blocks/SM residency.
__global__ void __launch_bounds__(256, 3) k_main(const float4* __restrict__ vox,
                                                 const float2* __restrict__ cen,
                                                 const float* __restrict__ W,
                                                 float* __restrict__ out,
                                                 int N)
{
    __shared__ float stile[8][4][P_PTS];   // [warp][comp][point]

    int w    = threadIdx.x >> 5;
    int lane = threadIdx.x & 31;
    int stride = gridDim.x * 8;

    int c0 = lane, c1 = lane + 32;
    const float* wr0 = W + c0 * 9;
    const float* wr1 = W + c1 * 9;

    float s0 = g_st[c0],           s1 = g_st[c1];
    float t0 = g_st[C_OUT_N + c0], t1 = g_st[C_OUT_N + c1];

    float a04 = wr0[4], a05 = wr0[5], a06 = wr0[6], a07 = wr0[7], a08 = wr0[8];
    float a14 = wr1[4], a15 = wr1[5], a16 = wr1[6], a17 = wr1[7], a18 = wr1[8];

    // s-folded, duplicated GEMM weights
    float f00 = s0 * (wr0[0] + a04 + a07);
    float f01 = s0 * (wr0[1] + a05 + a08);
    float f02 = s0 * (wr0[2] + a06);
    float f03 = s0 * wr0[3];
    float f10 = s1 * (wr1[0] + a14 + a17);
    float f11 = s1 * (wr1[1] + a15 + a18);
    float f12 = s1 * (wr1[2] + a16);
    float f13 = s1 * wr1[3];
    ull w00 = pack2(f00, f00), w10 = pack2(f01, f01);
    ull w20 = pack2(f02, f02), w30 = pack2(f03, f03);
    ull w01 = pack2(f10, f10), w11 = pack2(f11, f11);
    ull w21 = pack2(f12, f12), w31 = pack2(f13, f13);

    // packed, s-folded, negated bias weights: sb = sum an_k * u_k
    ull an4 = pack2(-s0 * a04, -s1 * a14);
    ull an5 = pack2(-s0 * a05, -s1 * a15);
    ull an6 = pack2(-s0 * a06, -s1 * a16);
    ull an7 = pack2(-s0 * a07, -s1 * a17);
    ull an8 = pack2(-s0 * a08, -s1 * a18);

    float* sx  = stile[w][0];
    float* sy  = stile[w][1];
    float* sz  = stile[w][2];
    float* swv = stile[w][3];

    const float nanv = __int_as_float(0x7fffffff);

    int n = blockIdx.x * 8 + w;
    if (n >= N) return;

    float4 meta = g_meta[n];
    float4 v    = vox[(size_t)n * P_PTS + lane];

    while (true) {
        int npts = __float_as_int(meta.w);

        // prefetch next pillar's big loads
        int n2 = n + stride;
        bool more = (n2 < N);
        float4 meta2 = make_float4(0.f, 0.f, 0.f, 0.f);
        float4 v2    = meta2;
        if (more) {
            meta2 = g_meta[n2];
            v2    = vox[(size_t)n2 * P_PTS + lane];
        }

        // cen needed only after the inner loop; issue now, latency hidden
        float2 c = cen[n];

        // stage SoA; padded slots become NaN (ignored by fmaxf)
        bool valid = (lane < npts);
        sx[lane]  = valid ? v.x : nanv;
        sy[lane]  = valid ? v.y : nanv;
        sz[lane]  = valid ? v.z : nanv;
        swv[lane] = valid ? v.w : nanv;
        __syncwarp();

        int nloop = (npts + 3) & ~3;      // NaN slots beyond npts ignored

        float M0 = -FLT_MAX, M1 = -FLT_MAX;

        for (int p = 0; p < nloop; p += 4) {
            ulonglong2 qx = *(const ulonglong2*)(sx + p);
            ulonglong2 qy = *(const ulonglong2*)(sy + p);
            ulonglong2 qz = *(const ulonglong2*)(sz + p);
            ulonglong2 qw = *(const ulonglong2*)(swv + p);

            ull rA0 = ffma2(qx.x, w00, ffma2(qy.x, w10, ffma2(qz.x, w20, fmul2(qw.x, w30))));
            ull rB0 = ffma2(qx.y, w00, ffma2(qy.y, w10, ffma2(qz.y, w20, fmul2(qw.y, w30))));
            ull rA1 = ffma2(qx.x, w01, ffma2(qy.x, w11, ffma2(qz.x, w21, fmul2(qw.x, w31))));
            ull rB1 = ffma2(qx.y, w01, ffma2(qy.y, w11, ffma2(qz.y, w21, fmul2(qw.y, w31))));

            M0 = fmaxf(M0, fmaxf(hmax2(rA0), hmax2(rB0)));
            M1 = fmaxf(M1, fmaxf(hmax2(rA1), hmax2(rB1)));
        }
        __syncwarp();   // tile reads done before next iteration restages

        // packed s*bias for this lane's two channels
        ull b = ffma2(an4, pack2(meta.x, meta.x),
                ffma2(an5, pack2(meta.y, meta.y),
                ffma2(an6, pack2(meta.z, meta.z),
                ffma2(an7, pack2(c.x, c.x),
                fmul2(an8, pack2(c.y, c.y))))));
        float b0, b1;
        unpack2(b, b0, b1);

        float X0 = M0 + b0;
        float X1 = M1 + b1;
        if (npts < P_PTS) {   // reference's padded rows contribute s*x = 0
            X0 = fmaxf(X0, 0.f);
            X1 = fmaxf(X1, 0.f);
        }

        out[(size_t)n * C_OUT_N + c0] = fmaxf(X0 + t0, 0.f);
        out[(size_t)n * C_OUT_N + c1] = fmaxf(X1 + t1, 0.f);

        if (!more) break;
        n = n2; meta = meta2; v = v2;
    }
}

// ---------------- launch ----------------
extern "C" void kernel_launch(void* const* d_in, const int* in_sizes, int n_in,
                              void* d_out, int out_size)
{
    const float* voxels  = (const float*)d_in[0];
    const int*   npp     = (const int*)d_in[1];
    const float* centers = (const float*)d_in[2];
    const float* W       = (const float*)d_in[3];
    const float* gamma   = (const float*)d_in[4];
    const float* beta    = (const float*)d_in[5];
    float* out = (float*)d_out;

    int N = in_sizes[1];

    // g_acc is zero on first call (static init); k_bn re-zeroes after use.
    k_stats<<<(N + 63) / 64, 64>>>((const float4*)voxels, npp,
                                   (const float2*)centers, N);
    k_bn<<<1, 64>>>(W, gamma, beta, N);
    k_main<<<1184, 256>>>((const float4*)voxels, (const float2*)centers,
                          W, out, N);
}

// round 11
// speedup vs baseline: 1.4394x; 1.4394x over previous
#include <cuda_runtime.h>
#include <cfloat>

#define P_PTS    32
#define C_OUT_N  64
#define NACC     54
#define BN_EPS   1e-3
#define NMAX     262144
#define SW2      17            // float4 stride per staged pillar chunk (pad)

typedef unsigned long long ull;

__device__ float  g_acc[NACC];         // statically zero-initialized
__device__ float  g_st[2 * C_OUT_N];   // s[64], t[64]
__device__ float4 g_meta[NMAX];        // (mx, my, mz, npts-as-float-bits)

// ---------------- f32x2 helpers (sm_100+) ----------------
__device__ __forceinline__ ull pack2(float lo, float hi) {
    ull r;
    asm("mov.b64 %0, {%1, %2};" : "=l"(r) : "f"(lo), "f"(hi));
    return r;
}
__device__ __forceinline__ void unpack2(ull v, float& lo, float& hi) {
    asm("mov.b64 {%0, %1}, %2;" : "=f"(lo), "=f"(hi) : "l"(v));
}
__device__ __forceinline__ ull ffma2(ull a, ull b, ull c) {
    ull d;
    asm("fma.rn.f32x2 %0, %1, %2, %3;" : "=l"(d) : "l"(a), "l"(b), "l"(c));
    return d;
}
__device__ __forceinline__ ull fmul2(ull a, ull b) {
    ull d;
    asm("mul.rn.f32x2 %0, %1, %2;" : "=l"(d) : "l"(a), "l"(b));
    return d;
}
// max of the two packed halves (unpack is reg-pair aliasing, costs nothing)
__device__ __forceinline__ float hmax2(ull v) {
    float lo, hi;
    unpack2(v, lo, hi);
    return fmaxf(lo, hi);
}

// ---------------- kernel 1: moment sums (coalesced, chunked smem staging) ----
// 64-thread blocks, 2 warps, each warp owns 32 pillars; two 16-point chunks.
// Reference quirk preserved: u_xyz = (sum over ALL 32 slots)/npts;
// feature-side sums over valid points only. Also writes g_meta (mean + npts).
// REQUIRES g_acc zeroed on entry (static init on first call; k_bn re-zeroes
// after consuming on every call -> graph-replay deterministic).
__global__ void __launch_bounds__(64) k_stats(const float4* __restrict__ vox,
                                              const int* __restrict__ npp,
                                              const float2* __restrict__ cen,
                                              int N)
{
    __shared__ float4 stg[2][32 * SW2];
    __shared__ float  sred[2][NACC];

    int w    = threadIdx.x >> 5;
    int lane = threadIdx.x & 31;
    int pillarBase = blockIdx.x * 64 + w * 32;

    int n = pillarBase + lane;
    bool active = (n < N);
    int npts = 0;
    float cx = 0.f, cy = 0.f;
    if (active) {
        npts = npp[n];
        float2 c = cen[n];
        cx = c.x; cy = c.y;
    }

    float sv[4] = {0.f, 0.f, 0.f, 0.f};
    float sa[3] = {0.f, 0.f, 0.f};
    float g1[10];
#pragma unroll
    for (int i = 0; i < 10; i++) g1[i] = 0.f;

    float4* buf = stg[w];
    int half = lane >> 4;
    int pt   = lane & 15;

    for (int ck = 0; ck < 2; ck++) {
#pragma unroll 4
        for (int q = 0; q < 16; q++) {
            int pidx = pillarBase + 2 * q + half;
            if (pidx < N)
                buf[(2 * q + half) * SW2 + pt] =
                    vox[(size_t)pidx * P_PTS + ck * 16 + pt];
        }
        __syncwarp();

        const float4* my = &buf[lane * SW2];
#pragma unroll 8
        for (int p = 0; p < 16; p++) {
            float4 v = my[p];
            int gp = ck * 16 + p;
            if (active) {
                sa[0] += v.x; sa[1] += v.y; sa[2] += v.z;
                if (gp < npts) {
                    sv[0] += v.x; sv[1] += v.y; sv[2] += v.z; sv[3] += v.w;
                    g1[0] += v.x * v.x; g1[1] += v.x * v.y; g1[2] += v.x * v.z; g1[3] += v.x * v.w;
                    g1[4] += v.y * v.y; g1[5] += v.y * v.z; g1[6] += v.y * v.w;
                    g1[7] += v.z * v.z; g1[8] += v.z * v.w;
                    g1[9] += v.w * v.w;
                }
            }
        }
        __syncwarp();
    }

    float fn  = (float)npts;
    float inv = (npts > 0) ? (1.0f / fn) : 0.0f;
    float u[5] = {sa[0] * inv, sa[1] * inv, sa[2] * inv, cx, cy};

    if (active)
        g_meta[n] = make_float4(u[0], u[1], u[2], __int_as_float(npts));

    float acc[NACC];
    acc[0] = sv[0]; acc[1] = sv[1]; acc[2] = sv[2]; acc[3] = sv[3];
    acc[4] = fn * cx; acc[5] = fn * cy;
#pragma unroll
    for (int i = 0; i < 10; i++) acc[6 + i] = g1[i];
    {
        int idx = 16;
#pragma unroll
        for (int a = 0; a < 4; a++)
#pragma unroll
            for (int k = 0; k < 5; k++) acc[idx++] = sv[a] * u[k];
#pragma unroll
        for (int j = 0; j < 5; j++)
#pragma unroll
            for (int k = j; k < 5; k++) acc[idx++] = fn * u[j] * u[k];
    }
    acc[51] = sa[0]; acc[52] = sa[1]; acc[53] = sa[2];

#pragma unroll
    for (int i = 0; i < NACC; i++) {
#pragma unroll
        for (int off = 16; off; off >>= 1)
            acc[i] += __shfl_xor_sync(0xffffffffu, acc[i], off);
    }
    if (lane == 0) {
#pragma unroll
        for (int i = 0; i < NACC; i++) sred[w][i] = acc[i];
    }
    __syncthreads();
    if (threadIdx.x < NACC)
        atomicAdd(&g_acc[threadIdx.x], sred[0][threadIdx.x] + sred[1][threadIdx.x]);
}

// ---------------- kernel 2: solve BN affine per channel; re-zero g_acc ------
__global__ void k_bn(const float* __restrict__ W,
                     const float* __restrict__ gamma,
                     const float* __restrict__ beta,
                     int N)
{
    int o = threadIdx.x;

    double A[NACC];
    for (int i = 0; i < NACC; i++) A[i] = (double)g_acc[i];

    // all threads have consumed g_acc; re-zero for the next graph replay
    __syncthreads();
    if (o < NACC) g_acc[o] = 0.0f;

    if (o >= C_OUT_N) return;

    const float* w = W + o * 9;
    double w0 = w[0], w1 = w[1], w2 = w[2], w3 = w[3], w4 = w[4];
    double w5 = w[5], w6 = w[6], w7 = w[7], w8 = w[8];

    double Wp[4] = {w0 + w4 + w7, w1 + w5 + w8, w2 + w6, w3};
    double Wt[5] = {w4, w5, w6, w7, w8};

    double NP = (double)N * (double)P_PTS;

    double sumx = Wp[0] * A[0] + Wp[1] * A[1] + Wp[2] * A[2] + Wp[3] * A[3]
                - (Wt[0] * A[51] + Wt[1] * A[52] + Wt[2] * A[53]
                   + Wt[3] * A[4] + Wt[4] * A[5]);
    double mean = sumx / NP;

    const double* G1 = &A[6];
    double q1 = Wp[0] * Wp[0] * G1[0] + 2.0 * Wp[0] * Wp[1] * G1[1]
              + 2.0 * Wp[0] * Wp[2] * G1[2] + 2.0 * Wp[0] * Wp[3] * G1[3]
              + Wp[1] * Wp[1] * G1[4] + 2.0 * Wp[1] * Wp[2] * G1[5]
              + 2.0 * Wp[1] * Wp[3] * G1[6]
              + Wp[2] * Wp[2] * G1[7] + 2.0 * Wp[2] * Wp[3] * G1[8]
              + Wp[3] * Wp[3] * G1[9];

    double q2 = 0.0;
    for (int a = 0; a < 4; a++)
        for (int k = 0; k < 5; k++)
            q2 += Wp[a] * A[16 + a * 5 + k] * Wt[k];
    q2 *= -2.0;

    double q3 = 0.0;
    {
        int idx = 36;
        for (int j = 0; j < 5; j++)
            for (int k = j; k < 5; k++) {
                double f = (j == k) ? 1.0 : 2.0;
                q3 += f * Wt[j] * Wt[k] * A[idx++];
            }
    }

    double E2  = (q1 + q2 + q3) / NP;
    double var = E2 - mean * mean;
    double s   = (double)gamma[o] * rsqrt(var + BN_EPS);
    double t   = (double)beta[o] - mean * s;

    g_st[o]           = (float)s;
    g_st[C_OUT_N + o] = (float)t;
}

// ---------------- kernel 3: s-folded GEMM + max + relu ----------------
// One warp per pillar (grid-stride). Lane l owns channels {l, l+32}; points
// packed in pairs as f32x2 via SoA smem tile; padded slots staged NaN
// (fmaxf ignores them). BN scale s folded INTO the weights. Bias computed
// with SCALAR FMAs (saves the 10 packed bias-constant registers -> natural
// pressure under the 80-reg / 3-blocks-per-SM boundary; NO launch_bounds cap).
__global__ void __launch_bounds__(256) k_main(const float4* __restrict__ vox,
                                              const float2* __restrict__ cen,
                                              const float* __restrict__ W,
                                              float* __restrict__ out,
                                              int N)
{
    __shared__ float stile[8][4][P_PTS];   // [warp][comp][point]

    int w    = threadIdx.x >> 5;
    int lane = threadIdx.x & 31;
    int stride = gridDim.x * 8;

    int c0 = lane, c1 = lane + 32;
    const float* wr0 = W + c0 * 9;
    const float* wr1 = W + c1 * 9;

    float s0 = g_st[c0],           s1 = g_st[c1];
    float t0 = g_st[C_OUT_N + c0], t1 = g_st[C_OUT_N + c1];

    float a04 = wr0[4], a05 = wr0[5], a06 = wr0[6], a07 = wr0[7], a08 = wr0[8];
    float a14 = wr1[4], a15 = wr1[5], a16 = wr1[6], a17 = wr1[7], a18 = wr1[8];

    // s-folded, duplicated GEMM weights
    float f00 = s0 * (wr0[0] + a04 + a07);
    float f01 = s0 * (wr0[1] + a05 + a08);
    float f02 = s0 * (wr0[2] + a06);
    float f03 = s0 * wr0[3];
    float f10 = s1 * (wr1[0] + a14 + a17);
    float f11 = s1 * (wr1[1] + a15 + a18);
    float f12 = s1 * (wr1[2] + a16);
    float f13 = s1 * wr1[3];
    ull w00 = pack2(f00, f00), w10 = pack2(f01, f01);
    ull w20 = pack2(f02, f02), w30 = pack2(f03, f03);
    ull w01 = pack2(f10, f10), w11 = pack2(f11, f11);
    ull w21 = pack2(f12, f12), w31 = pack2(f13, f13);

    float* sx  = stile[w][0];
    float* sy  = stile[w][1];
    float* sz  = stile[w][2];
    float* swv = stile[w][3];

    const float nanv = __int_as_float(0x7fffffff);

    int n = blockIdx.x * 8 + w;
    if (n >= N) return;

    float4 meta = g_meta[n];
    float4 v    = vox[(size_t)n * P_PTS + lane];

    while (true) {
        int npts = __float_as_int(meta.w);

        // prefetch next pillar's big loads
        int n2 = n + stride;
        bool more = (n2 < N);
        float4 meta2 = make_float4(0.f, 0.f, 0.f, 0.f);
        float4 v2    = meta2;
        if (more) {
            meta2 = g_meta[n2];
            v2    = vox[(size_t)n2 * P_PTS + lane];
        }

        // cen needed only after the inner loop; issue now, latency hidden
        float2 c = cen[n];

        // stage SoA; padded slots become NaN (ignored by fmaxf)
        bool valid = (lane < npts);
        sx[lane]  = valid ? v.x : nanv;
        sy[lane]  = valid ? v.y : nanv;
        sz[lane]  = valid ? v.z : nanv;
        swv[lane] = valid ? v.w : nanv;
        __syncwarp();

        int nloop = (npts + 3) & ~3;      // NaN slots beyond npts ignored

        float M0 = -FLT_MAX, M1 = -FLT_MAX;

        for (int p = 0; p < nloop; p += 4) {
            ulonglong2 qx = *(const ulonglong2*)(sx + p);
            ulonglong2 qy = *(const ulonglong2*)(sy + p);
            ulonglong2 qz = *(const ulonglong2*)(sz + p);
            ulonglong2 qw = *(const ulonglong2*)(swv + p);

            ull rA0 = ffma2(qx.x, w00, ffma2(qy.x, w10, ffma2(qz.x, w20, fmul2(qw.x, w30))));
            ull rB0 = ffma2(qx.y, w00, ffma2(qy.y, w10, ffma2(qz.y, w20, fmul2(qw.y, w30))));
            ull rA1 = ffma2(qx.x, w01, ffma2(qy.x, w11, ffma2(qz.x, w21, fmul2(qw.x, w31))));
            ull rB1 = ffma2(qx.y, w01, ffma2(qy.y, w11, ffma2(qz.y, w21, fmul2(qw.y, w31))));

            M0 = fmaxf(M0, fmaxf(hmax2(rA0), hmax2(rB0)));
            M1 = fmaxf(M1, fmaxf(hmax2(rA1), hmax2(rB1)));
        }
        __syncwarp();   // tile reads done before next iteration restages

        // scalar s*bias for this lane's two channels
        float d0 = a04 * meta.x + a05 * meta.y + a06 * meta.z
                 + a07 * c.x   + a08 * c.y;
        float d1 = a14 * meta.x + a15 * meta.y + a16 * meta.z
                 + a17 * c.x   + a18 * c.y;
        float X0 = M0 - s0 * d0;
        float X1 = M1 - s1 * d1;
        if (npts < P_PTS) {   // reference's padded rows contribute s*x = 0
            X0 = fmaxf(X0, 0.f);
            X1 = fmaxf(X1, 0.f);
        }

        out[(size_t)n * C_OUT_N + c0] = fmaxf(X0 + t0, 0.f);
        out[(size_t)n * C_OUT_N + c1] = fmaxf(X1 + t1, 0.f);

        if (!more) break;
        n = n2; meta = meta2; v = v2;
    }
}

// ---------------- launch ----------------
extern "C" void kernel_launch(void* const* d_in, const int* in_sizes, int n_in,
                              void* d_out, int out_size)
{
    const float* voxels  = (const float*)d_in[0];
    const int*   npp     = (const int*)d_in[1];
    const float* centers = (const float*)d_in[2];
    const float* W       = (const float*)d_in[3];
    const float* gamma   = (const float*)d_in[4];
    const float* beta    = (const float*)d_in[5];
    float* out = (float*)d_out;

    int N = in_sizes[1];

    // g_acc is zero on first call (static init); k_bn re-zeroes after use.
    k_stats<<<(N + 63) / 64, 64>>>((const float4*)voxels, npp,
                                   (const float2*)centers, N);
    k_bn<<<1, 64>>>(W, gamma, beta, N);
    k_main<<<1184, 256>>>((const float4*)voxels, (const float2*)centers,
                          W, out, N);
}

// round 12
// speedup vs baseline: 1.4786x; 1.0272x over previous
#include <cuda_runtime.h>
#include <cfloat>

#define P_PTS    32
#define C_OUT_N  64
#define NACC     54
#define BN_EPS   1e-3
#define NMAX     262144
#define SW8      9             // float4 stride per staged 8-point pillar chunk

typedef unsigned long long ull;

__device__ float  g_acc[NACC];         // statically zero-initialized
__device__ float  g_st[2 * C_OUT_N];   // s[64], t[64]
__device__ float4 g_meta[NMAX];        // (mx, my, mz, npts-as-float-bits)

// ---------------- f32x2 helpers (sm_100+) ----------------
__device__ __forceinline__ ull pack2(float lo, float hi) {
    ull r;
    asm("mov.b64 %0, {%1, %2};" : "=l"(r) : "f"(lo), "f"(hi));
    return r;
}
__device__ __forceinline__ void unpack2(ull v, float& lo, float& hi) {
    asm("mov.b64 {%0, %1}, %2;" : "=f"(lo), "=f"(hi) : "l"(v));
}
__device__ __forceinline__ ull ffma2(ull a, ull b, ull c) {
    ull d;
    asm("fma.rn.f32x2 %0, %1, %2, %3;" : "=l"(d) : "l"(a), "l"(b), "l"(c));
    return d;
}
__device__ __forceinline__ ull fmul2(ull a, ull b) {
    ull d;
    asm("mul.rn.f32x2 %0, %1, %2;" : "=l"(d) : "l"(a), "l"(b));
    return d;
}
// max of the two packed halves (unpack is reg-pair aliasing, costs nothing)
__device__ __forceinline__ float hmax2(ull v) {
    float lo, hi;
    unpack2(v, lo, hi);
    return fmaxf(lo, hi);
}

__device__ __forceinline__ float warp_sum(float x) {
#pragma unroll
    for (int off = 16; off; off >>= 1)
        x += __shfl_xor_sync(0xffffffffu, x, off);
    return x;
}

// ---------------- kernel 1: moment sums (8-pt chunks, batched reduction) ----
// 64-thread blocks, 2 warps, each warp owns 32 pillars; four 8-point chunks
// (9.2 KB smem). Reductions done in 3 batches so only ~20 accumulators are
// live at once (register pressure -> residency).
// Reference quirk preserved: u_xyz = (sum over ALL 32 slots)/npts;
// feature-side sums over valid points only. Also writes g_meta (mean+npts).
// REQUIRES g_acc zeroed on entry (static init first call; k_bn re-zeroes).
__global__ void __launch_bounds__(64) k_stats(const float4* __restrict__ vox,
                                              const int* __restrict__ npp,
                                              const float2* __restrict__ cen,
                                              int N)
{
    __shared__ float4 stg[2][32 * SW8];
    __shared__ float  sred[2][NACC];

    int w    = threadIdx.x >> 5;
    int lane = threadIdx.x & 31;
    int pillarBase = blockIdx.x * 64 + w * 32;

    int n = pillarBase + lane;
    bool active = (n < N);
    int npts = 0;
    float cx = 0.f, cy = 0.f;
    if (active) {
        npts = npp[n];
        float2 c = cen[n];
        cx = c.x; cy = c.y;
    }

    float sv[4] = {0.f, 0.f, 0.f, 0.f};
    float sa[3] = {0.f, 0.f, 0.f};
    float g1[10];
#pragma unroll
    for (int i = 0; i < 10; i++) g1[i] = 0.f;

    float4* buf = stg[w];
    int quarter = lane >> 3;       // which pillar of the group of 4
    int pt      = lane & 7;        // point within the 8-pt chunk

    for (int ck = 0; ck < 4; ck++) {
        // stage: 8 rounds x (4 pillars x 8 points) per warp
#pragma unroll 4
        for (int q = 0; q < 8; q++) {
            int pidx = pillarBase + 4 * q + quarter;
            if (pidx < N)
                buf[(4 * q + quarter) * SW8 + pt] =
                    vox[(size_t)pidx * P_PTS + ck * 8 + pt];
        }
        __syncwarp();

        const float4* my = &buf[lane * SW8];
#pragma unroll 8
        for (int p = 0; p < 8; p++) {
            float4 v = my[p];
            int gp = ck * 8 + p;
            if (active) {
                sa[0] += v.x; sa[1] += v.y; sa[2] += v.z;
                if (gp < npts) {
                    sv[0] += v.x; sv[1] += v.y; sv[2] += v.z; sv[3] += v.w;
                    g1[0] += v.x * v.x; g1[1] += v.x * v.y; g1[2] += v.x * v.z; g1[3] += v.x * v.w;
                    g1[4] += v.y * v.y; g1[5] += v.y * v.z; g1[6] += v.y * v.w;
                    g1[7] += v.z * v.z; g1[8] += v.z * v.w;
                    g1[9] += v.w * v.w;
                }
            }
        }
        __syncwarp();
    }

    float fn  = (float)npts;
    float inv = (npts > 0) ? (1.0f / fn) : 0.0f;
    float u0 = sa[0] * inv, u1 = sa[1] * inv, u2 = sa[2] * inv;

    if (active)
        g_meta[n] = make_float4(u0, u1, u2, __int_as_float(npts));

    // ---- batch A: acc[0..15] = sv[4], fn*c[2], g1[10] (g1 dies after) ----
    {
        float b[16];
        b[0] = sv[0]; b[1] = sv[1]; b[2] = sv[2]; b[3] = sv[3];
        b[4] = fn * cx; b[5] = fn * cy;
#pragma unroll
        for (int i = 0; i < 10; i++) b[6 + i] = g1[i];
#pragma unroll
        for (int i = 0; i < 16; i++) b[i] = warp_sum(b[i]);
        if (lane == 0) {
#pragma unroll
            for (int i = 0; i < 16; i++) sred[w][i] = b[i];
        }
    }

    // ---- batch B: acc[16..35] = sv_a * u_k (sv dies after) ----
    {
        float uu[5] = {u0, u1, u2, cx, cy};
        float b[20];
        int idx = 0;
#pragma unroll
        for (int a = 0; a < 4; a++)
#pragma unroll
            for (int k = 0; k < 5; k++) b[idx++] = sv[a] * uu[k];
#pragma unroll
        for (int i = 0; i < 20; i++) b[i] = warp_sum(b[i]);
        if (lane == 0) {
#pragma unroll
            for (int i = 0; i < 20; i++) sred[w][16 + i] = b[i];
        }
    }

    // ---- batch C: acc[36..50] = fn*u_j*u_k, acc[51..53] = sa ----
    {
        float uu[5] = {u0, u1, u2, cx, cy};
        float b[18];
        int idx = 0;
#pragma unroll
        for (int j = 0; j < 5; j++)
#pragma unroll
            for (int k = j; k < 5; k++) b[idx++] = fn * uu[j] * uu[k];
        b[15] = sa[0]; b[16] = sa[1]; b[17] = sa[2];
#pragma unroll
        for (int i = 0; i < 18; i++) b[i] = warp_sum(b[i]);
        if (lane == 0) {
#pragma unroll
            for (int i = 0; i < 18; i++) sred[w][36 + i] = b[i];
        }
    }

    __syncthreads();
    if (threadIdx.x < NACC)
        atomicAdd(&g_acc[threadIdx.x], sred[0][threadIdx.x] + sred[1][threadIdx.x]);
}

// ---------------- kernel 2: solve BN affine per channel; re-zero g_acc ------
__global__ void k_bn(const float* __restrict__ W,
                     const float* __restrict__ gamma,
                     const float* __restrict__ beta,
                     int N)
{
    int o = threadIdx.x;

    double A[NACC];
    for (int i = 0; i < NACC; i++) A[i] = (double)g_acc[i];

    // all threads have consumed g_acc; re-zero for the next graph replay
    __syncthreads();
    if (o < NACC) g_acc[o] = 0.0f;

    if (o >= C_OUT_N) return;

    const float* w = W + o * 9;
    double w0 = w[0], w1 = w[1], w2 = w[2], w3 = w[3], w4 = w[4];
    double w5 = w[5], w6 = w[6], w7 = w[7], w8 = w[8];

    double Wp[4] = {w0 + w4 + w7, w1 + w5 + w8, w2 + w6, w3};
    double Wt[5] = {w4, w5, w6, w7, w8};

    double NP = (double)N * (double)P_PTS;

    double sumx = Wp[0] * A[0] + Wp[1] * A[1] + Wp[2] * A[2] + Wp[3] * A[3]
                - (Wt[0] * A[51] + Wt[1] * A[52] + Wt[2] * A[53]
                   + Wt[3] * A[4] + Wt[4] * A[5]);
    double mean = sumx / NP;

    const double* G1 = &A[6];
    double q1 = Wp[0] * Wp[0] * G1[0] + 2.0 * Wp[0] * Wp[1] * G1[1]
              + 2.0 * Wp[0] * Wp[2] * G1[2] + 2.0 * Wp[0] * Wp[3] * G1[3]
              + Wp[1] * Wp[1] * G1[4] + 2.0 * Wp[1] * Wp[2] * G1[5]
              + 2.0 * Wp[1] * Wp[3] * G1[6]
              + Wp[2] * Wp[2] * G1[7] + 2.0 * Wp[2] * Wp[3] * G1[8]
              + Wp[3] * Wp[3] * G1[9];

    double q2 = 0.0;
    for (int a = 0; a < 4; a++)
        for (int k = 0; k < 5; k++)
            q2 += Wp[a] * A[16 + a * 5 + k] * Wt[k];
    q2 *= -2.0;

    double q3 = 0.0;
    {
        int idx = 36;
        for (int j = 0; j < 5; j++)
            for (int k = j; k < 5; k++) {
                double f = (j == k) ? 1.0 : 2.0;
                q3 += f * Wt[j] * Wt[k] * A[idx++];
            }
    }

    double E2  = (q1 + q2 + q3) / NP;
    double var = E2 - mean * mean;
    double s   = (double)gamma[o] * rsqrt(var + BN_EPS);
    double t   = (double)beta[o] - mean * s;

    g_st[o]           = (float)s;
    g_st[C_OUT_N + o] = (float)t;
}

// ---------------- kernel 3: s-folded GEMM + max + relu ----------------
// One warp per pillar (grid-stride), NO prefetch (registers saved buy a 3rd
// resident block per SM). Lane l owns channels {l, l+32}; points packed in
// pairs as f32x2 via SoA smem tile; padded slots staged NaN (fmaxf ignores).
// BN scale s folded INTO the weights; scalar bias epilogue.
__global__ void __launch_bounds__(256) k_main(const float4* __restrict__ vox,
                                              const float2* __restrict__ cen,
                                              const float* __restrict__ W,
                                              float* __restrict__ out,
                                              int N)
{
    __shared__ float stile[8][4][P_PTS];   // [warp][comp][point]

    int w    = threadIdx.x >> 5;
    int lane = threadIdx.x & 31;
    int stride = gridDim.x * 8;

    int c0 = lane, c1 = lane + 32;
    const float* wr0 = W + c0 * 9;
    const float* wr1 = W + c1 * 9;

    float s0 = g_st[c0],           s1 = g_st[c1];
    float t0 = g_st[C_OUT_N + c0], t1 = g_st[C_OUT_N + c1];

    float a04 = wr0[4], a05 = wr0[5], a06 = wr0[6], a07 = wr0[7], a08 = wr0[8];
    float a14 = wr1[4], a15 = wr1[5], a16 = wr1[6], a17 = wr1[7], a18 = wr1[8];

    // s-folded, duplicated GEMM weights
    float f00 = s0 * (wr0[0] + a04 + a07);
    float f01 = s0 * (wr0[1] + a05 + a08);
    float f02 = s0 * (wr0[2] + a06);
    float f03 = s0 * wr0[3];
    float f10 = s1 * (wr1[0] + a14 + a17);
    float f11 = s1 * (wr1[1] + a15 + a18);
    float f12 = s1 * (wr1[2] + a16);
    float f13 = s1 * wr1[3];
    ull w00 = pack2(f00, f00), w10 = pack2(f01, f01);
    ull w20 = pack2(f02, f02), w30 = pack2(f03, f03);
    ull w01 = pack2(f10, f10), w11 = pack2(f11, f11);
    ull w21 = pack2(f12, f12), w31 = pack2(f13, f13);

    float* sx  = stile[w][0];
    float* sy  = stile[w][1];
    float* sz  = stile[w][2];
    float* swv = stile[w][3];

    const float nanv = __int_as_float(0x7fffffff);

    for (int n = blockIdx.x * 8 + w; n < N; n += stride) {
        float4 meta = g_meta[n];
        float4 v    = vox[(size_t)n * P_PTS + lane];
        float2 c    = cen[n];

        int npts = __float_as_int(meta.w);

        // stage SoA; padded slots become NaN (ignored by fmaxf)
        bool valid = (lane < npts);
        sx[lane]  = valid ? v.x : nanv;
        sy[lane]  = valid ? v.y : nanv;
        sz[lane]  = valid ? v.z : nanv;
        swv[lane] = valid ? v.w : nanv;
        __syncwarp();

        int nloop = (npts + 3) & ~3;      // NaN slots beyond npts ignored

        float M0 = -FLT_MAX, M1 = -FLT_MAX;

        for (int p = 0; p < nloop; p += 4) {
            ulonglong2 qx = *(const ulonglong2*)(sx + p);
            ulonglong2 qy = *(const ulonglong2*)(sy + p);
            ulonglong2 qz = *(const ulonglong2*)(sz + p);
            ulonglong2 qw = *(const ulonglong2*)(swv + p);

            ull rA0 = ffma2(qx.x, w00, ffma2(qy.x, w10, ffma2(qz.x, w20, fmul2(qw.x, w30))));
            ull rB0 = ffma2(qx.y, w00, ffma2(qy.y, w10, ffma2(qz.y, w20, fmul2(qw.y, w30))));
            ull rA1 = ffma2(qx.x, w01, ffma2(qy.x, w11, ffma2(qz.x, w21, fmul2(qw.x, w31))));
            ull rB1 = ffma2(qx.y, w01, ffma2(qy.y, w11, ffma2(qz.y, w21, fmul2(qw.y, w31))));

            M0 = fmaxf(M0, fmaxf(hmax2(rA0), hmax2(rB0)));
            M1 = fmaxf(M1, fmaxf(hmax2(rA1), hmax2(rB1)));
        }
        __syncwarp();   // tile reads done before next iteration restages

        // scalar s*bias for this lane's two channels
        float d0 = a04 * meta.x + a05 * meta.y + a06 * meta.z
                 + a07 * c.x   + a08 * c.y;
        float d1 = a14 * meta.x + a15 * meta.y + a16 * meta.z
                 + a17 * c.x   + a18 * c.y;
        float X0 = M0 - s0 * d0;
        float X1 = M1 - s1 * d1;
        if (npts < P_PTS) {   // reference's padded rows contribute s*x = 0
            X0 = fmaxf(X0, 0.f);
            X1 = fmaxf(X1, 0.f);
        }

        out[(size_t)n * C_OUT_N + c0] = fmaxf(X0 + t0, 0.f);
        out[(size_t)n * C_OUT_N + c1] = fmaxf(X1 + t1, 0.f);
    }
}

// ---------------- launch ----------------
extern "C" void kernel_launch(void* const* d_in, const int* in_sizes, int n_in,
                              void* d_out, int out_size)
{
    const float* voxels  = (const float*)d_in[0];
    const int*   npp     = (const int*)d_in[1];
    const float* centers = (const float*)d_in[2];
    const float* W       = (const float*)d_in[3];
    const float* gamma   = (const float*)d_in[4];
    const float* beta    = (const float*)d_in[5];
    float* out = (float*)d_out;

    int N = in_sizes[1];

    // g_acc is zero on first call (static init); k_bn re-zeroes after use.
    k_stats<<<(N + 63) / 64, 64>>>((const float4*)voxels, npp,
                                   (const float2*)centers, N);
    k_bn<<<1, 64>>>(W, gamma, beta, N);
    k_main<<<1184, 256>>>((const float4*)voxels, (const float2*)centers,
                          W, out, N);
}